// round 5
// baseline (speedup 1.0000x reference)
#include <cuda_runtime.h>
#include <cstdint>

// out[tok, :] = sum_{l=0..7} weight[l, x[tok, l], :]
//   x:      16384 tokens x 8 int32 indices
//   weight: (8, 1024, 1024) f32, 32 MB (L2-resident, partial L1 reuse)
//   out:    16384 x 1024 f32
//
// Persistent grid-stride kernel: 1184 CTAs (8 per SM), each processes ~14
// tokens. Next token's indices are prefetched while the current token's
// reduce+store retires, hiding the idx->address->load dependency chain.

static constexpr int NTOK = 8 * 2048;   // 16384
static constexpr int K    = 1024;
static constexpr int D4   = 1024 / 4;   // 256 float4 per row
static constexpr int GRID = 148 * 8;    // 1184 persistent CTAs

__global__ __launch_bounds__(256, 8)
void multi_embed_kernel(const int4* __restrict__ x4,
                        const float4* __restrict__ w,
                        float4* __restrict__ out)
{
    const int tid    = threadIdx.x;
    const int stride = gridDim.x;
    const float4* wt = w + tid;

    int tok = blockIdx.x;
    if (tok >= NTOK) return;

    // Prologue: indices for the first token (uniform 16B loads, warp-broadcast).
    int4 iA = __ldg(x4 + tok * 2);
    int4 iB = __ldg(x4 + tok * 2 + 1);

    while (true) {
        // Issue all 8 weight loads immediately (MLP=8).
        float4 a0 = __ldg(wt + (size_t)(0 * K + iA.x) * D4);
        float4 a1 = __ldg(wt + (size_t)(1 * K + iA.y) * D4);
        float4 a2 = __ldg(wt + (size_t)(2 * K + iA.z) * D4);
        float4 a3 = __ldg(wt + (size_t)(3 * K + iA.w) * D4);
        float4 b0 = __ldg(wt + (size_t)(4 * K + iB.x) * D4);
        float4 b1 = __ldg(wt + (size_t)(5 * K + iB.y) * D4);
        float4 b2 = __ldg(wt + (size_t)(6 * K + iB.z) * D4);
        float4 b3 = __ldg(wt + (size_t)(7 * K + iB.w) * D4);

        // Prefetch next token's indices while weight loads are in flight.
        const int next = tok + stride;
        const bool more = (next < NTOK);
        if (more) {
            iA = __ldg(x4 + next * 2);
            iB = __ldg(x4 + next * 2 + 1);
        }

        float4 acc;
        acc.x = (a0.x + a1.x) + (a2.x + a3.x);
        acc.y = (a0.y + a1.y) + (a2.y + a3.y);
        acc.z = (a0.z + a1.z) + (a2.z + a3.z);
        acc.w = (a0.w + a1.w) + (a2.w + a3.w);
        acc.x += (b0.x + b1.x) + (b2.x + b3.x);
        acc.y += (b0.y + b1.y) + (b2.y + b3.y);
        acc.z += (b0.z + b1.z) + (b2.z + b3.z);
        acc.w += (b0.w + b1.w) + (b2.w + b3.w);

        // Streaming store: evict-first, keep weight table resident in L2.
        float4* dst = out + (size_t)tok * D4 + tid;
        asm volatile("st.global.cs.v4.f32 [%0], {%1, %2, %3, %4};"
                     :: "l"(dst), "f"(acc.x), "f"(acc.y), "f"(acc.z), "f"(acc.w)
                     : "memory");

        if (!more) break;
        tok = next;
    }
}

extern "C" void kernel_launch(void* const* d_in, const int* in_sizes, int n_in,
                              void* d_out, int out_size)
{
    const int4*   x = (const int4*)d_in[0];
    const float4* w = (const float4*)d_in[1];
    float4*       o = (float4*)d_out;

    multi_embed_kernel<<<GRID, 256>>>(x, w, o);
}

// round 6
// speedup vs baseline: 1.0595x; 1.0595x over previous
#include <cuda_runtime.h>
#include <cstdint>

// out[tok, :] = sum_{l=0..7} weight[l, x[tok, l], :]
//   x:      16384 tokens x 8 int32 indices
//   weight: (8, 1024, 1024) f32, 32 MB (L2-resident, significant L1 reuse)
//   out:    16384 x 1024 f32
//
// R4 shape (best measured: one CTA per token, grid=16384) + L1 eviction
// steering: weight rows evict_last (pinned-ish in L1), output evict_first.

static constexpr int NTOK = 8 * 2048;   // 16384
static constexpr int K    = 1024;
static constexpr int D4   = 1024 / 4;   // 256 float4 per row

__device__ __forceinline__ float4 ldg_evict_last(const float4* p)
{
    float4 v;
    asm volatile("ld.global.nc.L1::evict_last.v4.f32 {%0, %1, %2, %3}, [%4];"
                 : "=f"(v.x), "=f"(v.y), "=f"(v.z), "=f"(v.w)
                 : "l"(p));
    return v;
}

__global__ __launch_bounds__(256, 8)
void multi_embed_kernel(const int4* __restrict__ x4,
                        const float4* __restrict__ w,
                        float4* __restrict__ out)
{
    const int tok = blockIdx.x;
    const int tid = threadIdx.x;

    // All 8 indices via two uniform 16B loads (warp-broadcast).
    const int4 iA = __ldg(x4 + tok * 2);       // l = 0..3
    const int4 iB = __ldg(x4 + tok * 2 + 1);   // l = 4..7

    const float4* wt = w + tid;

    // 8 independent LDG.128 front-batched (MLP=8), evict_last in L1.
    float4 a0 = ldg_evict_last(wt + (size_t)(0 * K + iA.x) * D4);
    float4 a1 = ldg_evict_last(wt + (size_t)(1 * K + iA.y) * D4);
    float4 a2 = ldg_evict_last(wt + (size_t)(2 * K + iA.z) * D4);
    float4 a3 = ldg_evict_last(wt + (size_t)(3 * K + iA.w) * D4);
    float4 b0 = ldg_evict_last(wt + (size_t)(4 * K + iB.x) * D4);
    float4 b1 = ldg_evict_last(wt + (size_t)(5 * K + iB.y) * D4);
    float4 b2 = ldg_evict_last(wt + (size_t)(6 * K + iB.z) * D4);
    float4 b3 = ldg_evict_last(wt + (size_t)(7 * K + iB.w) * D4);

    float4 acc;
    acc.x = (a0.x + a1.x) + (a2.x + a3.x);
    acc.y = (a0.y + a1.y) + (a2.y + a3.y);
    acc.z = (a0.z + a1.z) + (a2.z + a3.z);
    acc.w = (a0.w + a1.w) + (a2.w + a3.w);

    acc.x += (b0.x + b1.x) + (b2.x + b3.x);
    acc.y += (b0.y + b1.y) + (b2.y + b3.y);
    acc.z += (b0.z + b1.z) + (b2.z + b3.z);
    acc.w += (b0.w + b1.w) + (b2.w + b3.w);

    // Streaming store: evict-first, don't displace weight lines.
    float4* dst = out + (size_t)tok * D4 + tid;
    asm volatile("st.global.cs.v4.f32 [%0], {%1, %2, %3, %4};"
                 :: "l"(dst), "f"(acc.x), "f"(acc.y), "f"(acc.z), "f"(acc.w)
                 : "memory");
}

extern "C" void kernel_launch(void* const* d_in, const int* in_sizes, int n_in,
                              void* d_out, int out_size)
{
    const int4*   x = (const int4*)d_in[0];
    const float4* w = (const float4*)d_in[1];
    float4*       o = (float4*)d_out;

    multi_embed_kernel<<<NTOK, 256>>>(x, w, o);
}